// round 1
// baseline (speedup 1.0000x reference)
#include <cuda_runtime.h>
#include <cuda_bf16.h>

// LSS voxel pooling: x[B,N,D,H,W,C] scatter-added by integer voxel coords into
// a [B, C*NZ, NX, NY] BEV grid. Shapes fixed by the problem:
constexpr int Bv = 4;
constexpr int Nc = 6, Dd = 41, Hh = 16, Ww = 44;
constexpr int Cc = 64;
constexpr int NXv = 200, NYv = 200;            // NZ = 1
constexpr int PER_B  = Nc * Dd * Hh * Ww;      // 173,184 points per batch
constexpr int NPRIME = Bv * PER_B;             // 692,736 points total
constexpr int XY = NXv * NYv;                  // 40,000 bins per batch
constexpr int OUT_ELEMS = Bv * Cc * XY;        // 10,240,000 floats

// Scratch accumulator in [B, X, Y, C] layout (C contiguous -> coalesced vector
// atomics). 41 MB static device array (allowed; no runtime allocation).
__device__ float g_scratch[Bv * XY * Cc];

// ---------------------------------------------------------------------------
// Kernel 1: zero the scratch accumulator (must run every graph replay).
// ---------------------------------------------------------------------------
__global__ void lss_zero_kernel() {
    int i = blockIdx.x * blockDim.x + threadIdx.x;
    // OUT_ELEMS / 4 float4 stores
    if (i < OUT_ELEMS / 4) {
        reinterpret_cast<float4*>(g_scratch)[i] = make_float4(0.f, 0.f, 0.f, 0.f);
    }
}

// ---------------------------------------------------------------------------
// Kernel 2: scatter-add. 16 threads per point; each thread moves one float4
// (4 channels) with a single red.global.add.v4.f32. Per point: 256 B fully
// coalesced read of x, 256 B contiguous vector-atomic into scratch.
// ---------------------------------------------------------------------------
__global__ void lss_scatter_kernel(const float4* __restrict__ x,
                                   const int*    __restrict__ geom) {
    long long t = (long long)blockIdx.x * blockDim.x + threadIdx.x;
    int p   = (int)(t >> 4);        // point index
    int sub = (int)(t & 15);        // float4 lane within the 64-channel vector
    if (p >= NPRIME) return;

    // geom_feats[..., 3] = (gx, gy, gz); broadcast loads (same addr per group)
    int gx = geom[3 * p + 0];
    int gy = geom[3 * p + 1];
    int gz = geom[3 * p + 2];
    // LSS 'kept' filter (reference adds zeros for dropped points == skip)
    if ((unsigned)gx >= (unsigned)NXv) return;
    if ((unsigned)gy >= (unsigned)NYv) return;
    if ((unsigned)gz >= 1u) return;   // NZ == 1

    int b = p / PER_B;                // constant divisor -> strength-reduced

    float4 v = x[(long long)p * 16 + sub];

    float* dst = &g_scratch[((((long long)b * NXv + gx) * NYv + gy) * Cc) + sub * 4];
    asm volatile("red.global.add.v4.f32 [%0], {%1,%2,%3,%4};"
                 :: "l"(dst), "f"(v.x), "f"(v.y), "f"(v.z), "f"(v.w)
                 : "memory");
}

// ---------------------------------------------------------------------------
// Kernel 3: transpose scratch [B, XY, C] -> out [B, C, XY].
// Standard 32x32 shared-memory tile, padded to kill bank conflicts.
// Grid: (XY/32 = 1250, C/32 = 2, B = 4); block (32, 8).
// ---------------------------------------------------------------------------
__global__ void lss_transpose_kernel(float* __restrict__ out) {
    __shared__ float tile[32][33];

    int b   = blockIdx.z;
    int c0  = blockIdx.y * 32;
    int xy0 = blockIdx.x * 32;
    int tx = threadIdx.x;
    int ty = threadIdx.y;

    const float* src = g_scratch + (long long)b * XY * Cc;
    float*       dst = out       + (long long)b * Cc * XY;

    #pragma unroll
    for (int j = 0; j < 32; j += 8) {
        // src row stride = 64 floats; tx contiguous -> 128B coalesced
        tile[ty + j][tx] = src[(long long)(xy0 + ty + j) * Cc + (c0 + tx)];
    }
    __syncthreads();
    #pragma unroll
    for (int j = 0; j < 32; j += 8) {
        // dst row stride = 40000 floats; tx contiguous -> 128B coalesced
        dst[(long long)(c0 + ty + j) * XY + (xy0 + tx)] = tile[tx][ty + j];
    }
}

// ---------------------------------------------------------------------------
// Launch: zero -> scatter -> transpose (implicit stream ordering).
// ---------------------------------------------------------------------------
extern "C" void kernel_launch(void* const* d_in, const int* in_sizes, int n_in,
                              void* d_out, int out_size) {
    const float4* x    = (const float4*)d_in[0];   // x: [B,N,D,H,W,C] fp32
    const int*    geom = (const int*)d_in[1];      // geom_feats: [...,3] int32
    float*        out  = (float*)d_out;            // [B, C, NX, NY] fp32

    {
        int n4 = OUT_ELEMS / 4;
        lss_zero_kernel<<<(n4 + 255) / 256, 256>>>();
    }
    {
        long long threads = (long long)NPRIME * 16;
        int blocks = (int)((threads + 255) / 256);
        lss_scatter_kernel<<<blocks, 256>>>(x, geom);
    }
    {
        dim3 tb(32, 8);
        dim3 tg(XY / 32, Cc / 32, Bv);
        lss_transpose_kernel<<<tg, tb>>>(out);
    }
}

// round 2
// speedup vs baseline: 1.1058x; 1.1058x over previous
#include <cuda_runtime.h>
#include <cuda_bf16.h>

// LSS voxel pooling, gather formulation:
//   1) zero per-bin counters
//   2) build fixed-capacity per-bin point lists (int atomics only)
//   3) gather-reduce each bin in registers, write output directly in
//      [B, C, X, Y] layout (coalesced via smem staging tile)
//   4) overflow fallback (float atomics) for bins with >CAP points (never
//      expected at lambda=4.33, but required for correctness in general)
constexpr int Bv = 4;
constexpr int Nc = 6, Dd = 41, Hh = 16, Ww = 44;
constexpr int Cc = 64;
constexpr int NXv = 200, NYv = 200;              // NZ = 1
constexpr int PER_B  = Nc * Dd * Hh * Ww;        // 173,184 points per batch
constexpr int NPRIME = Bv * PER_B;               // 692,736 points
constexpr int XY     = NXv * NYv;                // 40,000 bins per batch
constexpr int NBINS  = Bv * XY;                  // 160,000 bins
constexpr int CAP    = 32;                       // slots per bin (P(ovf)~1e-22)
constexpr int OVF_MAX = 4096;

__device__ int g_counts[NBINS];                  // 640 KB
__device__ int g_slots[NBINS * CAP];             // 20.5 MB (sparsely written)
__device__ int g_ovf_n;
__device__ int g_ovf[OVF_MAX];

// ---------------------------------------------------------------------------
// Kernel 1: zero counters + overflow cursor (tiny: 640 KB).
// ---------------------------------------------------------------------------
__global__ void lss_zero_counts() {
    int i = blockIdx.x * blockDim.x + threadIdx.x;
    if (i < NBINS) g_counts[i] = 0;
    if (i == 0) g_ovf_n = 0;
}

// ---------------------------------------------------------------------------
// Kernel 2: build per-bin point lists. One thread per point; int atomicAdd
// gives the slot rank. Only geom is read here (8.3 MB).
// ---------------------------------------------------------------------------
__global__ void lss_build(const int* __restrict__ geom) {
    int p = blockIdx.x * blockDim.x + threadIdx.x;
    if (p >= NPRIME) return;
    int gx = geom[3 * p + 0];
    int gy = geom[3 * p + 1];
    int gz = geom[3 * p + 2];
    if ((unsigned)gx >= (unsigned)NXv) return;   // LSS 'kept' filter
    if ((unsigned)gy >= (unsigned)NYv) return;
    if ((unsigned)gz >= 1u) return;              // NZ == 1
    int b   = p / PER_B;
    int bin = b * XY + gx * NYv + gy;
    int r = atomicAdd(&g_counts[bin], 1);
    if (r < CAP) {
        g_slots[bin * CAP + r] = p;
    } else {
        int o = atomicAdd(&g_ovf_n, 1);
        if (o < OVF_MAX) g_ovf[o] = p;
    }
}

// ---------------------------------------------------------------------------
// Kernel 3: gather-reduce. Block = 512 threads = 32 bins x 16 subs; each
// thread accumulates one float4 (4 channels) over its bin's point list.
// Point reads are 256 B contiguous per point (16 lanes x float4).
// Output written directly in [B, C, XY] layout: stage the 32x64 tile in
// smem, then write with 32 consecutive-xy lanes per channel (128 B stores).
// XY % 32 == 0, so all 32 bins of a block share the same batch b.
// ---------------------------------------------------------------------------
__global__ void lss_gather(const float4* __restrict__ x,
                           float* __restrict__ out) {
    __shared__ float s[32][65];                  // +1 pad: conflict-free read

    int bL  = threadIdx.x >> 4;                  // bin within block (0..31)
    int sub = threadIdx.x & 15;                  // float4 lane (0..15)
    int bin = blockIdx.x * 32 + bL;

    int cnt = g_counts[bin];
    if (cnt > CAP) cnt = CAP;

    float4 acc = make_float4(0.f, 0.f, 0.f, 0.f);
    const int* sl = &g_slots[bin * CAP];
    for (int i = 0; i < cnt; ++i) {
        int p = sl[i];                           // broadcast within 16 lanes
        float4 v = x[(long long)p * 16 + sub];   // 256 B contiguous per point
        acc.x += v.x; acc.y += v.y; acc.z += v.z; acc.w += v.w;
    }

    s[bL][sub * 4 + 0] = acc.x;
    s[bL][sub * 4 + 1] = acc.y;
    s[bL][sub * 4 + 2] = acc.z;
    s[bL][sub * 4 + 3] = acc.w;
    __syncthreads();

    int bin0 = blockIdx.x * 32;
    int b    = bin0 / XY;
    int xy0  = bin0 - b * XY;
    int c    = threadIdx.x >> 5;                 // 0..15
    int bb   = threadIdx.x & 31;                 // xy lane 0..31

    float* dst = out + (long long)b * Cc * XY + xy0 + bb;
    #pragma unroll
    for (int it = 0; it < 4; ++it) {
        int cc = c + 16 * it;
        dst[(long long)cc * XY] = s[bb][cc];     // coalesced: 32 lanes x 4 B
    }
}

// ---------------------------------------------------------------------------
// Kernel 4: overflow fallback. Expected n==0; float atomics into out.
// Must run AFTER lss_gather (out fully written by then).
// ---------------------------------------------------------------------------
__global__ void lss_overflow(const float* __restrict__ x,
                             const int*   __restrict__ geom,
                             float* __restrict__ out) {
    int n = g_ovf_n;
    if (n > OVF_MAX) n = OVF_MAX;
    int stride = blockDim.x * gridDim.x;
    for (int i = blockIdx.x * blockDim.x + threadIdx.x; i < n * Cc; i += stride) {
        int idx = i / Cc, c = i % Cc;
        int p  = g_ovf[idx];
        int gx = geom[3 * p + 0];
        int gy = geom[3 * p + 1];
        int b  = p / PER_B;
        atomicAdd(&out[((long long)b * Cc + c) * XY + gx * NYv + gy],
                  x[(long long)p * Cc + c]);
    }
}

// ---------------------------------------------------------------------------
extern "C" void kernel_launch(void* const* d_in, const int* in_sizes, int n_in,
                              void* d_out, int out_size) {
    const float4* x4   = (const float4*)d_in[0];
    const float*  xf   = (const float*)d_in[0];
    const int*    geom = (const int*)d_in[1];
    float*        out  = (float*)d_out;

    lss_zero_counts<<<(NBINS + 1023) / 1024, 1024>>>();
    lss_build<<<(NPRIME + 255) / 256, 256>>>(geom);
    lss_gather<<<NBINS / 32, 512>>>(x4, out);
    lss_overflow<<<16, 256>>>(xf, geom, out);
}

// round 3
// speedup vs baseline: 1.4062x; 1.2717x over previous
#include <cuda_runtime.h>
#include <cuda_bf16.h>

// LSS voxel pooling, gather formulation v2:
//   1) zero per-bin counters (640 KB)
//   2) build fixed-capacity per-bin point lists (int atomics only)
//   3) gather-reduce each bin with MLP-4 loads, in-kernel overflow fallback,
//      write output directly in [B, C, X, Y] layout (coalesced via smem tile)
constexpr int Bv = 4;
constexpr int Nc = 6, Dd = 41, Hh = 16, Ww = 44;
constexpr int Cc = 64;
constexpr int NXv = 200, NYv = 200;              // NZ = 1
constexpr int PER_B  = Nc * Dd * Hh * Ww;        // 173,184 points per batch
constexpr int NPRIME = Bv * PER_B;               // 692,736 points
constexpr int XY     = NXv * NYv;                // 40,000 bins per batch
constexpr int NBINS  = Bv * XY;                  // 160,000 bins
constexpr int CAP    = 16;                       // 64 B slot line per bin
constexpr int OVF_MAX = 4096;

__device__ int g_counts[NBINS];                  // 640 KB
__device__ int g_slots[NBINS * CAP];             // 10.2 MB
__device__ int g_ovf_n;
__device__ int g_ovf[OVF_MAX];

// ---------------------------------------------------------------------------
// Kernel 1: zero counters + overflow cursor.
// ---------------------------------------------------------------------------
__global__ void lss_zero_counts() {
    int i = blockIdx.x * blockDim.x + threadIdx.x;
    if (i < NBINS) g_counts[i] = 0;
    if (i == 0) g_ovf_n = 0;
}

// ---------------------------------------------------------------------------
// Kernel 2: build per-bin point lists. One thread per point.
// ---------------------------------------------------------------------------
__global__ void lss_build(const int* __restrict__ geom) {
    int p = blockIdx.x * blockDim.x + threadIdx.x;
    if (p >= NPRIME) return;
    int gx = geom[3 * p + 0];
    int gy = geom[3 * p + 1];
    int gz = geom[3 * p + 2];
    if ((unsigned)gx >= (unsigned)NXv) return;   // LSS 'kept' filter
    if ((unsigned)gy >= (unsigned)NYv) return;
    if ((unsigned)gz >= 1u) return;              // NZ == 1
    int b   = p / PER_B;
    int bin = b * XY + gx * NYv + gy;
    int r = atomicAdd(&g_counts[bin], 1);
    if (r < CAP) {
        g_slots[bin * CAP + r] = p;
    } else {
        int o = atomicAdd(&g_ovf_n, 1);
        if (o < OVF_MAX) g_ovf[o] = p;
    }
}

// ---------------------------------------------------------------------------
// Kernel 3: gather-reduce. Block = 512 threads = 32 bins x 16 subs; each
// thread owns one float4 (4 channels) of its bin. Slot list loaded as int4
// (whole list = one 64 B line), giving 4 independent x-loads per iteration.
// Overflow bins (cnt > CAP, expected ~0) additionally scan the global
// overflow list in-kernel -- no separate fallback launch.
// Output staged in smem, then written in [B, C, XY] layout, 128 B coalesced.
// ---------------------------------------------------------------------------
__global__ void lss_gather(const float4* __restrict__ x,
                           const int*    __restrict__ geom,
                           float* __restrict__ out) {
    __shared__ float s[32][65];                  // +1 pad: conflict-free read

    int bL  = threadIdx.x >> 4;                  // bin within block (0..31)
    int sub = threadIdx.x & 15;                  // float4 lane (0..15)
    int bin = blockIdx.x * 32 + bL;

    int cnt  = g_counts[bin];
    int cnt0 = cnt < CAP ? cnt : CAP;

    float4 acc = make_float4(0.f, 0.f, 0.f, 0.f);
    const int4* sl4 = (const int4*)&g_slots[bin * CAP];

    for (int i = 0; i < cnt0; i += 4) {
        int4 ps = sl4[i >> 2];                   // one 16 B load covers 4 slots
        // 4 independent predicated loads -> MLP 4
        {
            float4 v = x[(long long)ps.x * 16 + sub];
            acc.x += v.x; acc.y += v.y; acc.z += v.z; acc.w += v.w;
        }
        if (i + 1 < cnt0) {
            float4 v = x[(long long)ps.y * 16 + sub];
            acc.x += v.x; acc.y += v.y; acc.z += v.z; acc.w += v.w;
        }
        if (i + 2 < cnt0) {
            float4 v = x[(long long)ps.z * 16 + sub];
            acc.x += v.x; acc.y += v.y; acc.z += v.z; acc.w += v.w;
        }
        if (i + 3 < cnt0) {
            float4 v = x[(long long)ps.w * 16 + sub];
            acc.x += v.x; acc.y += v.y; acc.z += v.z; acc.w += v.w;
        }
    }

    if (cnt > CAP) {                             // expected never; correctness net
        int n = g_ovf_n;
        if (n > OVF_MAX) n = OVF_MAX;
        for (int i = 0; i < n; ++i) {
            int p  = g_ovf[i];
            int gx = geom[3 * p + 0];
            int gy = geom[3 * p + 1];
            int b  = p / PER_B;
            if (b * XY + gx * NYv + gy == bin) {
                float4 v = x[(long long)p * 16 + sub];
                acc.x += v.x; acc.y += v.y; acc.z += v.z; acc.w += v.w;
            }
        }
    }

    s[bL][sub * 4 + 0] = acc.x;
    s[bL][sub * 4 + 1] = acc.y;
    s[bL][sub * 4 + 2] = acc.z;
    s[bL][sub * 4 + 3] = acc.w;
    __syncthreads();

    int bin0 = blockIdx.x * 32;
    int b    = bin0 / XY;                        // XY % 32 == 0: same b per block
    int xy0  = bin0 - b * XY;
    int c    = threadIdx.x >> 5;                 // 0..15
    int bb   = threadIdx.x & 31;                 // xy lane 0..31

    float* dst = out + (long long)b * Cc * XY + xy0 + bb;
    #pragma unroll
    for (int it = 0; it < 4; ++it) {
        int cc = c + 16 * it;
        dst[(long long)cc * XY] = s[bb][cc];     // 32 lanes x 4 B = 128 B store
    }
}

// ---------------------------------------------------------------------------
extern "C" void kernel_launch(void* const* d_in, const int* in_sizes, int n_in,
                              void* d_out, int out_size) {
    const float4* x4   = (const float4*)d_in[0];
    const int*    geom = (const int*)d_in[1];
    float*        out  = (float*)d_out;

    lss_zero_counts<<<(NBINS + 1023) / 1024, 1024>>>();
    lss_build<<<(NPRIME + 255) / 256, 256>>>(geom);
    lss_gather<<<NBINS / 32, 512>>>(x4, geom, out);
}